// round 7
// baseline (speedup 1.0000x reference)
#include <cuda_runtime.h>
#include <cuda_fp16.h>

// RoIMaskAlign via NHWC-fp16 staging, round 7: branch-free gather, MLP=8/sy.
// features (B=2, C=256, H=200, W=272) fp32, rois (K, 5) fp32
// out (K, C, 14, 14) fp32
// PH=PW=14, SPATIAL_SCALE=0.25, SR=2, SPATIAL_SHIFT=0, HALF_PART=0, ROI_SCALE=1.2

#define PH 14
#define PW 14

static constexpr int   Bc = 2;
static constexpr int   Cc = 256;
static constexpr int   Hc = 200;
static constexpr int   Wc = 272;
static constexpr float SCALE     = 0.25f;
static constexpr float ROI_SCALE = 1.2f;

// NHWC fp16 scratch: (B, H, W, C) = 2*200*272*256 halves = 55.7 MB
__device__ __align__(16) __half g_nhwc[(size_t)Bc * Hc * Wc * Cc];

// ---------------------------------------------------------------------------
// Kernel 1: NCHW fp32 -> NHWC fp16 transpose (unchanged).
// ---------------------------------------------------------------------------
__global__ __launch_bounds__(256)
void transpose_kernel(const float* __restrict__ feat)
{
    __shared__ __align__(16) __half s[16][264];

    int x0 = blockIdx.x * 16;
    int y  = blockIdx.y;
    int b  = blockIdx.z;
    int tid = threadIdx.x;
    int xl = tid & 15;
    int ci = tid >> 4;

    const float* fp = feat + (((size_t)b * Cc) * Hc + y) * Wc + x0 + xl;
    #pragma unroll
    for (int k = 0; k < 16; k++) {
        int c = k * 16 + ci;
        s[xl][c] = __float2half_rn(__ldg(fp + (size_t)c * (Hc * Wc)));
    }
    __syncthreads();

    __half* op = g_nhwc + (((size_t)b * Hc + y) * Wc + x0) * Cc;
    #pragma unroll
    for (int j = 0; j < 2; j++) {
        int u = tid + j * 256;
        int x = u >> 5;
        int k = u & 31;
        *reinterpret_cast<uint4*>(op + (size_t)x * Cc + k * 8) =
            *reinterpret_cast<const uint4*>(&s[x][k * 8]);
    }
}

// Accumulate 8 fp16 channels of one tap into 8 float accumulators.
__device__ __forceinline__ void acc_tap(const uint4& v, float wt,
                                        float& a0, float& a1, float& a2, float& a3,
                                        float& a4, float& a5, float& a6, float& a7)
{
    const __half2* h = reinterpret_cast<const __half2*>(&v);
    float2 f0 = __half22float2(h[0]);
    float2 f1 = __half22float2(h[1]);
    float2 f2 = __half22float2(h[2]);
    float2 f3 = __half22float2(h[3]);
    a0 = fmaf(wt, f0.x, a0); a1 = fmaf(wt, f0.y, a1);
    a2 = fmaf(wt, f1.x, a2); a3 = fmaf(wt, f1.y, a3);
    a4 = fmaf(wt, f2.x, a4); a5 = fmaf(wt, f2.y, a5);
    a6 = fmaf(wt, f3.x, a6); a7 = fmaf(wt, f3.y, a7);
}

// ---------------------------------------------------------------------------
// Kernel 2: gather. Block = (n, ph); 14 warps, warp = pw.
// Branch-free: validity folds to weight 0. Per sy, all 8 tap loads are
// issued back-to-back (MLP=8) before consumption.
// ---------------------------------------------------------------------------
__global__ __launch_bounds__(448, 3)
void gather_kernel(const float* __restrict__ rois,
                   float* __restrict__ out)
{
    __shared__ __align__(16) float s[PW][264];

    int n  = blockIdx.x;
    int ph = blockIdx.y;
    int pw   = threadIdx.x >> 5;   // 0..13
    int lane = threadIdx.x & 31;

    // ---- ROI geometry (identical across the warp) ----
    const float* r = rois + n * 5;
    int   b  = (int)r[0];
    float rx1 = r[1], ry1 = r[2], rx2 = r[3], ry2 = r[4];

    float cx = (rx1 + rx2) * 0.5f;
    float cy = (ry1 + ry2) * 0.5f;
    float rw = (rx2 - rx1) * ROI_SCALE;
    float rh = (ry2 - ry1) * ROI_SCALE;
    float x1s = (cx - 0.5f * rw) * SCALE;
    float x2s = (cx + 0.5f * rw) * SCALE;
    float y1s = (cy - 0.5f * rh) * SCALE;
    float y2s = (cy + 0.5f * rh) * SCALE;

    float roi_w = fmaxf(x2s - x1s, 1.0f);
    float roi_h = fmaxf(y2s - y1s, 1.0f);
    float bin_w = roi_w * (1.0f / PW);
    float bin_h = roi_h * (1.0f / PH);

    const __half* tb = g_nhwc + (size_t)lane * 8;

    float a0=0.f,a1=0.f,a2=0.f,a3=0.f,a4=0.f,a5=0.f,a6=0.f,a7=0.f;

    // per-sample x data (shared across sy)
    int   xi0[2], xi1[2];
    float lx[2], hx[2];
    float mx[2];                 // 0.25 if x-valid else 0 (mean folded in)
    #pragma unroll
    for (int sx = 0; sx < 2; sx++) {
        float x = x1s + ((float)pw + ((float)sx + 0.5f) * 0.5f) * bin_w;
        mx[sx] = ((x > -1.0f) && (x < (float)Wc)) ? 0.25f : 0.0f;
        float xc = fminf(fmaxf(x, 0.0f), (float)(Wc - 1));
        int x0 = (int)floorf(xc);
        xi0[sx] = x0;
        xi1[sx] = min(x0 + 1, Wc - 1);
        lx[sx] = xc - (float)x0;
        hx[sx] = 1.0f - lx[sx];
    }

    #pragma unroll
    for (int sy = 0; sy < 2; sy++) {
        float y = y1s + ((float)ph + (sy ? 0.75f : 0.25f)) * bin_h;
        float vyf = ((y > -1.0f) && (y < (float)Hc)) ? 1.0f : 0.0f;
        float yc = fminf(fmaxf(y, 0.0f), (float)(Hc - 1));
        int y0 = (int)floorf(yc);
        int y1b = min(y0 + 1, Hc - 1);
        float ly = yc - (float)y0;
        float hy = 1.0f - ly;

        size_t rb0 = ((size_t)(b * Hc + y0)  * Wc) << 8;
        size_t rb1 = ((size_t)(b * Hc + y1b) * Wc) << 8;

        // weights (validity + mean folded)
        float m0 = vyf * mx[0];
        float m1 = vyf * mx[1];
        float wA00 = m0 * hy * hx[0], wA01 = m0 * hy * lx[0];
        float wA10 = m0 * ly * hx[0], wA11 = m0 * ly * lx[0];
        float wB00 = m1 * hy * hx[1], wB01 = m1 * hy * lx[1];
        float wB10 = m1 * ly * hx[1], wB11 = m1 * ly * lx[1];

        // 8 loads issued back-to-back (MLP = 8)
        uint4 vA00 = __ldg((const uint4*)(tb + rb0 + (((size_t)xi0[0]) << 8)));
        uint4 vA01 = __ldg((const uint4*)(tb + rb0 + (((size_t)xi1[0]) << 8)));
        uint4 vA10 = __ldg((const uint4*)(tb + rb1 + (((size_t)xi0[0]) << 8)));
        uint4 vA11 = __ldg((const uint4*)(tb + rb1 + (((size_t)xi1[0]) << 8)));
        uint4 vB00 = __ldg((const uint4*)(tb + rb0 + (((size_t)xi0[1]) << 8)));
        uint4 vB01 = __ldg((const uint4*)(tb + rb0 + (((size_t)xi1[1]) << 8)));
        uint4 vB10 = __ldg((const uint4*)(tb + rb1 + (((size_t)xi0[1]) << 8)));
        uint4 vB11 = __ldg((const uint4*)(tb + rb1 + (((size_t)xi1[1]) << 8)));

        acc_tap(vA00, wA00, a0,a1,a2,a3,a4,a5,a6,a7);
        acc_tap(vA01, wA01, a0,a1,a2,a3,a4,a5,a6,a7);
        acc_tap(vA10, wA10, a0,a1,a2,a3,a4,a5,a6,a7);
        acc_tap(vA11, wA11, a0,a1,a2,a3,a4,a5,a6,a7);
        acc_tap(vB00, wB00, a0,a1,a2,a3,a4,a5,a6,a7);
        acc_tap(vB01, wB01, a0,a1,a2,a3,a4,a5,a6,a7);
        acc_tap(vB10, wB10, a0,a1,a2,a3,a4,a5,a6,a7);
        acc_tap(vB11, wB11, a0,a1,a2,a3,a4,a5,a6,a7);
    }

    // stash as (pw, c); mean already folded into weights
    *reinterpret_cast<float4*>(&s[pw][lane * 8])     = make_float4(a0, a1, a2, a3);
    *reinterpret_cast<float4*>(&s[pw][lane * 8 + 4]) = make_float4(a4, a5, a6, a7);

    __syncthreads();

    // out[(n*C + c)*196 + ph*14 + pw]
    for (int c = threadIdx.x; c < Cc; c += 448) {
        size_t o = ((size_t)n * Cc + c) * (PH * PW) + ph * PW;
        #pragma unroll
        for (int p = 0; p < 7; p++) {
            *reinterpret_cast<float2*>(out + o + 2 * p) =
                make_float2(s[2 * p][c], s[2 * p + 1][c]);
        }
    }
}

extern "C" void kernel_launch(void* const* d_in, const int* in_sizes, int n_in,
                              void* d_out, int out_size)
{
    const float* feat = (const float*)d_in[0];
    const float* rois = (const float*)d_in[1];
    float* out = (float*)d_out;

    int K = in_sizes[1] / 5;

    dim3 tg(Wc / 16, Hc, Bc);          // 17 x 200 x 2
    transpose_kernel<<<tg, 256>>>(feat);

    dim3 gg(K, PH);                    // K x 14
    gather_kernel<<<gg, 448>>>(rois, out);
}